// round 10
// baseline (speedup 1.0000x reference)
#include <cuda_runtime.h>
#include <cuda_bf16.h>

#define NN 100000
#define EE 1600000
#define HH 64
#define CC 64
#define PP 32
#define SCAN_BLOCKS ((NN + 1023) / 1024)   // 98

// Scratch (allocation-free rule: __device__ globals)
__device__ float g_agg[(size_t)NN * HH];   // mean-aggregated features, 25.6 MB
__device__ int   g_count[NN];
__device__ int   g_off[NN + 1];
__device__ int   g_cur[NN];
__device__ int   g_csr[EE];
__device__ int   g_bsum[SCAN_BLOCKS];
__device__ int   g_bpre[SCAN_BLOCKS];
__device__ int   g_is64;                   // edge_index dtype flag

// ---------------------------------------------------------------------------
// Kernel 0: detect int64 vs int32 edge_index (odd int32 words all zero => i64)
// ---------------------------------------------------------------------------
__global__ void detect_kernel(const int* __restrict__ ei32) {
    if (threadIdx.x == 0 && blockIdx.x == 0) {
        int odd_nonzero = 0;
        for (int i = 0; i < 256; i++)
            if (ei32[2 * i + 1] != 0) odd_nonzero++;
        g_is64 = (odd_nonzero == 0) ? 1 : 0;
    }
}

__device__ __forceinline__ void load_edge(const int* __restrict__ ei32, int e,
                                          int& src, int& dst) {
    if (g_is64) {   // uniform branch
        src = ei32[2 * (size_t)e];
        dst = ei32[2 * ((size_t)EE + e)];
    } else {
        src = ei32[e];
        dst = ei32[(size_t)EE + e];
    }
}

__global__ void zero_counts_kernel() {
    int i = blockIdx.x * blockDim.x + threadIdx.x;
    if (i < NN) g_count[i] = 0;
}

__global__ void hist_kernel(const int* __restrict__ ei32) {
    int e = blockIdx.x * blockDim.x + threadIdx.x;
    if (e >= EE) return;
    int src, dst;
    load_edge(ei32, e, src, dst);
    if ((unsigned)dst < NN) atomicAdd(&g_count[dst], 1);
}

// ---------------------------------------------------------------------------
// 3-pass hierarchical exclusive scan of counts -> offsets (+cursors)
// ---------------------------------------------------------------------------
__global__ __launch_bounds__(1024) void scan1_kernel() {
    __shared__ int sh[1024];
    int t = threadIdx.x;
    int i = blockIdx.x * 1024 + t;
    int c = (i < NN) ? g_count[i] : 0;
    sh[t] = c;
    __syncthreads();
#pragma unroll
    for (int off = 1; off < 1024; off <<= 1) {
        int v = (t >= off) ? sh[t - off] : 0;
        __syncthreads();
        sh[t] += v;
        __syncthreads();
    }
    if (i < NN) g_off[i] = sh[t] - c;        // exclusive, block-local
    if (t == 1023) g_bsum[blockIdx.x] = sh[1023];
}

__global__ __launch_bounds__(128) void scan2_kernel() {
    __shared__ int sh[128];
    int t = threadIdx.x;
    int v = (t < SCAN_BLOCKS) ? g_bsum[t] : 0;
    sh[t] = v;
    __syncthreads();
#pragma unroll
    for (int off = 1; off < 128; off <<= 1) {
        int p = (t >= off) ? sh[t - off] : 0;
        __syncthreads();
        sh[t] += p;
        __syncthreads();
    }
    if (t < SCAN_BLOCKS) g_bpre[t] = sh[t] - v;   // exclusive prefix
    if (t == 127) g_off[NN] = sh[127];
}

__global__ __launch_bounds__(1024) void scan3_kernel() {
    int i = blockIdx.x * 1024 + threadIdx.x;
    if (i >= NN) return;
    int o = g_off[i] + g_bpre[blockIdx.x];
    g_off[i] = o;
    g_cur[i] = o;
}

__global__ void fill_kernel(const int* __restrict__ ei32) {
    int e = blockIdx.x * blockDim.x + threadIdx.x;
    if (e >= EE) return;
    int src, dst;
    load_edge(ei32, e, src, dst);
    if ((unsigned)dst >= NN) return;
    int pos = atomicAdd(&g_cur[dst], 1);
    g_csr[pos] = src;
}

// ---------------------------------------------------------------------------
// Pull-aggregate (unchanged from R7, passed).  One warp per 2 nodes; 16 lanes
// own one float4 each; writes MEAN once, no atomics.
// ---------------------------------------------------------------------------
__global__ __launch_bounds__(256) void pull_kernel(const float4* __restrict__ x4) {
    int gw = (blockIdx.x * blockDim.x + threadIdx.x) >> 5;   // global warp id
    int lane = threadIdx.x & 31;
    int n = gw * 2 + (lane >> 4);
    int hl = lane & 15;
    if (n >= NN) return;

    int s = g_off[n];
    int epos = g_off[n + 1];
    float4 acc = make_float4(0.f, 0.f, 0.f, 0.f);
#pragma unroll 4
    for (int p = s; p < epos; p++) {
        int src = __ldg(&g_csr[p]);
        if ((unsigned)src < NN) {
            float4 v = __ldg(&x4[(size_t)src * 16 + hl]);
            acc.x += v.x; acc.y += v.y; acc.z += v.z; acc.w += v.w;
        }
    }
    float inv = 1.0f / fmaxf((float)(epos - s), 1.0f);
    reinterpret_cast<float4*>(g_agg)[(size_t)n * 16 + hl] =
        make_float4(acc.x * inv, acc.y * inv, acc.z * inv, acc.w * inv);
}

// ---------------------------------------------------------------------------
// Fused update + head.  Static smem 41 KB (no opt-in needed).
// GEMM: 4 threads per 4-node group, each owns a 16-wide j-quarter (as R7).
// Head: x_new stays in registers; cross-quarter reduction via shfl.xor over
// the 4 lanes of the group.  No early return before shuffles (clamped loads,
// guarded stores) so warp masks stay full.
// ---------------------------------------------------------------------------
__global__ __launch_bounds__(128) void update_head_kernel(
    const float* __restrict__ u,
    const float* __restrict__ W,
    const float* __restrict__ B,
    const float* __restrict__ b,
    const float* __restrict__ Wp,
    const float* __restrict__ bp,
    float* __restrict__ out) {
    __shared__ float Ws[HH * HH];      // 16 KB  W[k][j]
    __shared__ float Bs[CC * HH];      // 16 KB  B[k][j]
    __shared__ float Wps[HH * PP];     //  8 KB  Wp[j][p]
    __shared__ float bs[HH];
    __shared__ float bps[PP];

    int tid = threadIdx.x;
    for (int i = tid; i < HH * HH; i += 128) { Ws[i] = W[i]; Bs[i] = B[i]; }
    for (int i = tid; i < HH * PP; i += 128) Wps[i] = Wp[i];
    if (tid < HH) bs[tid] = b[tid];
    if (tid < PP) bps[tid] = bp[tid];
    __syncthreads();

    int grp = tid >> 2;                 // 0..31  -> node group
    int jq  = tid & 3;                  // j-quarter: [jq*16, jq*16+16)
    int n0  = blockIdx.x * 128 + grp * 4;
    int nn[4];
#pragma unroll
    for (int i = 0; i < 4; i++) nn[i] = min(n0 + i, NN - 1);

    const float4* Ws4 = reinterpret_cast<const float4*>(Ws);
    const float4* Bs4 = reinterpret_cast<const float4*>(Bs);
    const float4* mean4 = reinterpret_cast<const float4*>(g_agg);
    const float4* u4    = reinterpret_cast<const float4*>(u);

    float acc[4][16];
#pragma unroll
    for (int i = 0; i < 4; i++)
#pragma unroll
        for (int j = 0; j < 16; j++) acc[i][j] = bs[jq * 16 + j];

#pragma unroll 1
    for (int kc = 0; kc < 16; kc++) {
        float4 mv[4], uv[4];
#pragma unroll
        for (int i = 0; i < 4; i++) {
            mv[i] = __ldg(&mean4[(size_t)nn[i] * 16 + kc]);
            uv[i] = __ldg(&u4[(size_t)nn[i] * 16 + kc]);
        }
#pragma unroll
        for (int q = 0; q < 4; q++) {
            int base = (kc * 4 + q) * 16 + jq * 4;
            float4 w0 = Ws4[base + 0], w1 = Ws4[base + 1];
            float4 w2 = Ws4[base + 2], w3 = Ws4[base + 3];
            float4 b0 = Bs4[base + 0], b1 = Bs4[base + 1];
            float4 b2 = Bs4[base + 2], b3 = Bs4[base + 3];
#pragma unroll
            for (int i = 0; i < 4; i++) {
                float mk = reinterpret_cast<const float*>(&mv[i])[q];
                float uk = reinterpret_cast<const float*>(&uv[i])[q];
                acc[i][0]  += mk * w0.x + uk * b0.x;
                acc[i][1]  += mk * w0.y + uk * b0.y;
                acc[i][2]  += mk * w0.z + uk * b0.z;
                acc[i][3]  += mk * w0.w + uk * b0.w;
                acc[i][4]  += mk * w1.x + uk * b1.x;
                acc[i][5]  += mk * w1.y + uk * b1.y;
                acc[i][6]  += mk * w1.z + uk * b1.z;
                acc[i][7]  += mk * w1.w + uk * b1.w;
                acc[i][8]  += mk * w2.x + uk * b2.x;
                acc[i][9]  += mk * w2.y + uk * b2.y;
                acc[i][10] += mk * w2.z + uk * b2.z;
                acc[i][11] += mk * w2.w + uk * b2.w;
                acc[i][12] += mk * w3.x + uk * b3.x;
                acc[i][13] += mk * w3.y + uk * b3.y;
                acc[i][14] += mk * w3.z + uk * b3.z;
                acc[i][15] += mk * w3.w + uk * b3.w;
            }
        }
    }

    // ReLU in registers; write x_new
#pragma unroll
    for (int i = 0; i < 4; i++)
#pragma unroll
        for (int j = 0; j < 16; j++) acc[i][j] = fmaxf(acc[i][j], 0.f);

#pragma unroll
    for (int i = 0; i < 4; i++) {
        if (n0 + i < NN) {
            float4* o = reinterpret_cast<float4*>(out) + (size_t)(n0 + i) * 16 + jq * 4;
#pragma unroll
            for (int j4 = 0; j4 < 4; j4++)
                o[j4] = make_float4(acc[i][j4 * 4 + 0], acc[i][j4 * 4 + 1],
                                    acc[i][j4 * 4 + 2], acc[i][j4 * 4 + 3]);
        }
    }

    // ---- head: y[n] = x_new[n] @ Wp + bp, reduced across the 4 group lanes ----
    const float4* Wps4 = reinterpret_cast<const float4*>(Wps);
#pragma unroll 1
    for (int i = 0; i < 4; i++) {
        float p[PP];
#pragma unroll
        for (int pp = 0; pp < PP; pp++) p[pp] = 0.f;
#pragma unroll
        for (int jl = 0; jl < 16; jl++) {
            float xv = acc[i][jl];
            int j = jq * 16 + jl;
#pragma unroll
            for (int p4 = 0; p4 < 8; p4++) {
                float4 wp = Wps4[j * 8 + p4];
                p[p4 * 4 + 0] += xv * wp.x;
                p[p4 * 4 + 1] += xv * wp.y;
                p[p4 * 4 + 2] += xv * wp.z;
                p[p4 * 4 + 3] += xv * wp.w;
            }
        }
        // reduce partial sums across lanes {jq=0..3} of this group
#pragma unroll
        for (int pp = 0; pp < PP; pp++) {
            p[pp] += __shfl_xor_sync(0xffffffffu, p[pp], 1);
            p[pp] += __shfl_xor_sync(0xffffffffu, p[pp], 2);
        }
        int n = n0 + i;
        if (n < NN) {
            // every lane now holds the full y; lane jq writes its 8-wide slice
            float4* yo = reinterpret_cast<float4*>(out + (size_t)NN * HH) +
                         (size_t)n * 8 + jq * 2;
            yo[0] = make_float4(p[jq * 8 + 0] + bps[jq * 8 + 0],
                                p[jq * 8 + 1] + bps[jq * 8 + 1],
                                p[jq * 8 + 2] + bps[jq * 8 + 2],
                                p[jq * 8 + 3] + bps[jq * 8 + 3]);
            yo[1] = make_float4(p[jq * 8 + 4] + bps[jq * 8 + 4],
                                p[jq * 8 + 5] + bps[jq * 8 + 5],
                                p[jq * 8 + 6] + bps[jq * 8 + 6],
                                p[jq * 8 + 7] + bps[jq * 8 + 7]);
        }
    }
}

// ---------------------------------------------------------------------------
// Launch
// Inputs: x, u, edge_index ([2,E], int32/int64 autodetected), W, B, b, Wp, bp
// Output: x_new [N*64] then y [N*32]  (float32)
// ---------------------------------------------------------------------------
extern "C" void kernel_launch(void* const* d_in, const int* in_sizes, int n_in,
                              void* d_out, int out_size) {
    const float* x       = (const float*)d_in[0];
    const float* u       = (const float*)d_in[1];
    const int*   ei32    = (const int*)d_in[2];
    const float* W       = (const float*)d_in[3];
    const float* B       = (const float*)d_in[4];
    const float* b       = (const float*)d_in[5];
    const float* Wp      = (const float*)d_in[6];
    const float* bp      = (const float*)d_in[7];
    float* out           = (float*)d_out;

    detect_kernel<<<1, 32>>>(ei32);
    zero_counts_kernel<<<(NN + 255) / 256, 256>>>();
    hist_kernel<<<(EE + 255) / 256, 256>>>(ei32);
    scan1_kernel<<<SCAN_BLOCKS, 1024>>>();
    scan2_kernel<<<1, 128>>>();
    scan3_kernel<<<SCAN_BLOCKS, 1024>>>();
    fill_kernel<<<(EE + 255) / 256, 256>>>(ei32);

    long long pull_threads = (long long)((NN + 1) / 2) * 32;
    pull_kernel<<<(int)((pull_threads + 255) / 256), 256>>>((const float4*)x);

    update_head_kernel<<<(NN + 127) / 128, 128>>>(u, W, B, b, Wp, bp, out);
}

// round 12
// speedup vs baseline: 1.5411x; 1.5411x over previous
#include <cuda_runtime.h>
#include <cuda_bf16.h>

#define NN 100000
#define EE 1600000
#define HH 64
#define CC 64
#define PP 32
#define SCAN_BLOCKS ((NN + 1023) / 1024)   // 98

// Scratch (allocation-free rule: __device__ globals)
__device__ float g_agg[(size_t)NN * HH];   // mean-aggregated features, 25.6 MB
__device__ int   g_count[NN];
__device__ int   g_off[NN + 1];
__device__ int   g_cur[NN];
__device__ int   g_csr[EE];
__device__ int   g_bsum[SCAN_BLOCKS];
__device__ int   g_bpre[SCAN_BLOCKS];
__device__ int   g_is64;                   // edge_index dtype flag

// ---------------------------------------------------------------------------
// Kernel 1: zero per-node counters + detect edge_index dtype (block 0 thread 0:
// int64 little-endian with values < 2^31 has all-odd int32 words zero).
// ---------------------------------------------------------------------------
__global__ void zero_counts_kernel(const int* __restrict__ ei32) {
    int i = blockIdx.x * blockDim.x + threadIdx.x;
    if (i < NN) g_count[i] = 0;
    if (i == 0) {
        int odd_nonzero = 0;
        for (int k = 0; k < 256; k++)
            if (ei32[2 * k + 1] != 0) odd_nonzero++;
        g_is64 = (odd_nonzero == 0) ? 1 : 0;
    }
}

__device__ __forceinline__ void load_edge(const int* __restrict__ ei32, int e,
                                          int& src, int& dst) {
    if (g_is64) {   // uniform branch
        src = ei32[2 * (size_t)e];
        dst = ei32[2 * ((size_t)EE + e)];
    } else {
        src = ei32[e];
        dst = ei32[(size_t)EE + e];
    }
}

__global__ void hist_kernel(const int* __restrict__ ei32) {
    int e = blockIdx.x * blockDim.x + threadIdx.x;
    if (e >= EE) return;
    int src, dst;
    load_edge(ei32, e, src, dst);
    if ((unsigned)dst < NN) atomicAdd(&g_count[dst], 1);
}

// ---------------------------------------------------------------------------
// 3-pass hierarchical exclusive scan of counts -> offsets (+cursors)
// ---------------------------------------------------------------------------
__global__ __launch_bounds__(1024) void scan1_kernel() {
    __shared__ int sh[1024];
    int t = threadIdx.x;
    int i = blockIdx.x * 1024 + t;
    int c = (i < NN) ? g_count[i] : 0;
    sh[t] = c;
    __syncthreads();
#pragma unroll
    for (int off = 1; off < 1024; off <<= 1) {
        int v = (t >= off) ? sh[t - off] : 0;
        __syncthreads();
        sh[t] += v;
        __syncthreads();
    }
    if (i < NN) g_off[i] = sh[t] - c;        // exclusive, block-local
    if (t == 1023) g_bsum[blockIdx.x] = sh[1023];
}

__global__ __launch_bounds__(128) void scan2_kernel() {
    __shared__ int sh[128];
    int t = threadIdx.x;
    int v = (t < SCAN_BLOCKS) ? g_bsum[t] : 0;
    sh[t] = v;
    __syncthreads();
#pragma unroll
    for (int off = 1; off < 128; off <<= 1) {
        int p = (t >= off) ? sh[t - off] : 0;
        __syncthreads();
        sh[t] += p;
        __syncthreads();
    }
    if (t < SCAN_BLOCKS) g_bpre[t] = sh[t] - v;   // exclusive prefix
    if (t == 127) g_off[NN] = sh[127];
}

__global__ __launch_bounds__(1024) void scan3_kernel() {
    int i = blockIdx.x * 1024 + threadIdx.x;
    if (i >= NN) return;
    int o = g_off[i] + g_bpre[blockIdx.x];
    g_off[i] = o;
    g_cur[i] = o;
}

__global__ void fill_kernel(const int* __restrict__ ei32) {
    int e = blockIdx.x * blockDim.x + threadIdx.x;
    if (e >= EE) return;
    int src, dst;
    load_edge(ei32, e, src, dst);
    if ((unsigned)dst >= NN) return;
    int pos = atomicAdd(&g_cur[dst], 1);
    g_csr[pos] = src;
}

// ---------------------------------------------------------------------------
// Pull-aggregate (R7, verified).  One warp per 2 nodes; 16 lanes own one
// float4 each; writes MEAN once, no atomics.
// ---------------------------------------------------------------------------
__global__ __launch_bounds__(256) void pull_kernel(const float4* __restrict__ x4) {
    int gw = (blockIdx.x * blockDim.x + threadIdx.x) >> 5;   // global warp id
    int lane = threadIdx.x & 31;
    int n = gw * 2 + (lane >> 4);
    int hl = lane & 15;
    if (n >= NN) return;

    int s = g_off[n];
    int epos = g_off[n + 1];
    float4 acc = make_float4(0.f, 0.f, 0.f, 0.f);
#pragma unroll 4
    for (int p = s; p < epos; p++) {
        int src = __ldg(&g_csr[p]);
        if ((unsigned)src < NN) {
            float4 v = __ldg(&x4[(size_t)src * 16 + hl]);
            acc.x += v.x; acc.y += v.y; acc.z += v.z; acc.w += v.w;
        }
    }
    float inv = 1.0f / fmaxf((float)(epos - s), 1.0f);
    reinterpret_cast<float4*>(g_agg)[(size_t)n * 16 + hl] =
        make_float4(acc.x * inv, acc.y * inv, acc.z * inv, acc.w * inv);
}

// ---------------------------------------------------------------------------
// Update: x_new = relu(mean @ W + u @ B + b).
// 4 threads per 4-node group; each thread owns a 16-wide j-quarter for FOUR
// nodes -> per k: 8 LDS.128 feed 128 FFMA (16:1).  256 threads/block
// (256 nodes/block) for better latency hiding at the same 33 KB smem.
// ---------------------------------------------------------------------------
__global__ __launch_bounds__(256) void update_kernel(
    const float* __restrict__ u,
    const float* __restrict__ W,
    const float* __restrict__ B,
    const float* __restrict__ b,
    float* __restrict__ out) {
    __shared__ float Ws[HH * HH];      // 16 KB  W[k][j]
    __shared__ float Bs[CC * HH];      // 16 KB  B[k][j]
    __shared__ float bs[HH];

    int tid = threadIdx.x;
    for (int i = tid; i < HH * HH; i += 256) { Ws[i] = W[i]; Bs[i] = B[i]; }
    if (tid < HH) bs[tid] = b[tid];
    __syncthreads();

    int grp = tid >> 2;                 // 0..63  -> node group
    int jq  = tid & 3;                  // j-quarter: [jq*16, jq*16+16)
    int n0  = blockIdx.x * 256 + grp * 4;
    if (n0 >= NN) return;
    int nn[4];
#pragma unroll
    for (int i = 0; i < 4; i++) nn[i] = min(n0 + i, NN - 1);

    const float4* Ws4 = reinterpret_cast<const float4*>(Ws);
    const float4* Bs4 = reinterpret_cast<const float4*>(Bs);
    const float4* mean4 = reinterpret_cast<const float4*>(g_agg);
    const float4* u4    = reinterpret_cast<const float4*>(u);

    float acc[4][16];
#pragma unroll
    for (int i = 0; i < 4; i++)
#pragma unroll
        for (int j = 0; j < 16; j++) acc[i][j] = bs[jq * 16 + j];

#pragma unroll 1
    for (int kc = 0; kc < 16; kc++) {
        float4 mv[4], uv[4];
#pragma unroll
        for (int i = 0; i < 4; i++) {
            mv[i] = __ldg(&mean4[(size_t)nn[i] * 16 + kc]);
            uv[i] = __ldg(&u4[(size_t)nn[i] * 16 + kc]);
        }
#pragma unroll
        for (int q = 0; q < 4; q++) {
            int base = (kc * 4 + q) * 16 + jq * 4;
            float4 w0 = Ws4[base + 0], w1 = Ws4[base + 1];
            float4 w2 = Ws4[base + 2], w3 = Ws4[base + 3];
            float4 b0 = Bs4[base + 0], b1 = Bs4[base + 1];
            float4 b2 = Bs4[base + 2], b3 = Bs4[base + 3];
#pragma unroll
            for (int i = 0; i < 4; i++) {
                float mk = reinterpret_cast<const float*>(&mv[i])[q];
                float uk = reinterpret_cast<const float*>(&uv[i])[q];
                acc[i][0]  += mk * w0.x + uk * b0.x;
                acc[i][1]  += mk * w0.y + uk * b0.y;
                acc[i][2]  += mk * w0.z + uk * b0.z;
                acc[i][3]  += mk * w0.w + uk * b0.w;
                acc[i][4]  += mk * w1.x + uk * b1.x;
                acc[i][5]  += mk * w1.y + uk * b1.y;
                acc[i][6]  += mk * w1.z + uk * b1.z;
                acc[i][7]  += mk * w1.w + uk * b1.w;
                acc[i][8]  += mk * w2.x + uk * b2.x;
                acc[i][9]  += mk * w2.y + uk * b2.y;
                acc[i][10] += mk * w2.z + uk * b2.z;
                acc[i][11] += mk * w2.w + uk * b2.w;
                acc[i][12] += mk * w3.x + uk * b3.x;
                acc[i][13] += mk * w3.y + uk * b3.y;
                acc[i][14] += mk * w3.z + uk * b3.z;
                acc[i][15] += mk * w3.w + uk * b3.w;
            }
        }
    }

#pragma unroll
    for (int i = 0; i < 4; i++) {
        if (n0 + i >= NN) break;
        float4* o = reinterpret_cast<float4*>(out) + (size_t)(n0 + i) * 16 + jq * 4;
#pragma unroll
        for (int j4 = 0; j4 < 4; j4++)
            o[j4] = make_float4(fmaxf(acc[i][j4 * 4 + 0], 0.f),
                                fmaxf(acc[i][j4 * 4 + 1], 0.f),
                                fmaxf(acc[i][j4 * 4 + 2], 0.f),
                                fmaxf(acc[i][j4 * 4 + 3], 0.f));
    }
}

// ---------------------------------------------------------------------------
// Head: y = x_new @ Wp + bp  (R7, verified).
// ---------------------------------------------------------------------------
__global__ __launch_bounds__(256) void head_kernel(
    const float* __restrict__ Wp,
    const float* __restrict__ bp,
    float* __restrict__ out) {
    __shared__ float Wps[HH * PP];     // 8 KB  Wp[j][p]
    __shared__ float bps[PP];

    int tid = threadIdx.x;
    for (int i = tid; i < HH * PP; i += 256) Wps[i] = Wp[i];
    if (tid < PP) bps[tid] = bp[tid];
    __syncthreads();

    int n = blockIdx.x * 256 + tid;
    if (n >= NN) return;

    const float4* Wps4 = reinterpret_cast<const float4*>(Wps);
    const float4* x4   = reinterpret_cast<const float4*>(out) + (size_t)n * 16;

    float yacc[PP];
#pragma unroll
    for (int p = 0; p < PP; p++) yacc[p] = bps[p];

#pragma unroll 1
    for (int jc = 0; jc < 16; jc++) {
        float4 xv = __ldg(&x4[jc]);
        float xs[4] = {xv.x, xv.y, xv.z, xv.w};
#pragma unroll
        for (int q = 0; q < 4; q++) {
            int j = jc * 4 + q;
#pragma unroll
            for (int p4 = 0; p4 < 8; p4++) {
                float4 wp = Wps4[j * 8 + p4];
                yacc[p4 * 4 + 0] += xs[q] * wp.x;
                yacc[p4 * 4 + 1] += xs[q] * wp.y;
                yacc[p4 * 4 + 2] += xs[q] * wp.z;
                yacc[p4 * 4 + 3] += xs[q] * wp.w;
            }
        }
    }

    float4* outy4 = reinterpret_cast<float4*>(out + (size_t)NN * HH) + (size_t)n * 8;
#pragma unroll
    for (int p4 = 0; p4 < 8; p4++)
        outy4[p4] = make_float4(yacc[p4 * 4 + 0], yacc[p4 * 4 + 1],
                                yacc[p4 * 4 + 2], yacc[p4 * 4 + 3]);
}

// ---------------------------------------------------------------------------
// Launch
// Inputs: x, u, edge_index ([2,E], int32/int64 autodetected), W, B, b, Wp, bp
// Output: x_new [N*64] then y [N*32]  (float32)
// ---------------------------------------------------------------------------
extern "C" void kernel_launch(void* const* d_in, const int* in_sizes, int n_in,
                              void* d_out, int out_size) {
    const float* x       = (const float*)d_in[0];
    const float* u       = (const float*)d_in[1];
    const int*   ei32    = (const int*)d_in[2];
    const float* W       = (const float*)d_in[3];
    const float* B       = (const float*)d_in[4];
    const float* b       = (const float*)d_in[5];
    const float* Wp      = (const float*)d_in[6];
    const float* bp      = (const float*)d_in[7];
    float* out           = (float*)d_out;

    zero_counts_kernel<<<(NN + 255) / 256, 256>>>(ei32);
    hist_kernel<<<(EE + 255) / 256, 256>>>(ei32);
    scan1_kernel<<<SCAN_BLOCKS, 1024>>>();
    scan2_kernel<<<1, 128>>>();
    scan3_kernel<<<SCAN_BLOCKS, 1024>>>();
    fill_kernel<<<(EE + 255) / 256, 256>>>(ei32);

    long long pull_threads = (long long)((NN + 1) / 2) * 32;
    pull_kernel<<<(int)((pull_threads + 255) / 256), 256>>>((const float4*)x);

    update_kernel<<<(NN + 255) / 256, 256>>>(u, W, B, b, out);
    head_kernel<<<(NN + 255) / 256, 256>>>(Wp, bp, out);
}

// round 13
// speedup vs baseline: 1.6169x; 1.0492x over previous
#include <cuda_runtime.h>
#include <cuda_bf16.h>

#define NN 100000
#define EE 1600000
#define HH 64
#define CC 64
#define PP 32
#define SCAN_BLOCKS ((NN + 1023) / 1024)   // 98

// Scratch (allocation-free rule: __device__ globals)
__device__ float g_agg[(size_t)NN * HH];   // mean-aggregated features, 25.6 MB
__device__ int   g_count[NN];
__device__ int   g_off[NN + 1];
__device__ int   g_cur[NN];
__device__ int   g_csr[EE];
__device__ int   g_bsum[SCAN_BLOCKS];
__device__ int   g_is64;                   // edge_index dtype flag

// ---------------------------------------------------------------------------
// Kernel 1: zero per-node counters + detect edge_index dtype (thread 0:
// int64 little-endian with values < 2^31 has all-odd int32 words zero).
// ---------------------------------------------------------------------------
__global__ void zero_counts_kernel(const int* __restrict__ ei32) {
    int i = blockIdx.x * blockDim.x + threadIdx.x;
    if (i < NN) g_count[i] = 0;
    if (i == 0) {
        int odd_nonzero = 0;
        for (int k = 0; k < 256; k++)
            if (ei32[2 * k + 1] != 0) odd_nonzero++;
        g_is64 = (odd_nonzero == 0) ? 1 : 0;
    }
}

__device__ __forceinline__ void load_edge(const int* __restrict__ ei32, int e,
                                          int& src, int& dst) {
    if (g_is64) {   // uniform branch
        src = ei32[2 * (size_t)e];
        dst = ei32[2 * ((size_t)EE + e)];
    } else {
        src = ei32[e];
        dst = ei32[(size_t)EE + e];
    }
}

__global__ void hist_kernel(const int* __restrict__ ei32) {
    int e = blockIdx.x * blockDim.x + threadIdx.x;
    if (e >= EE) return;
    int src, dst;
    load_edge(ei32, e, src, dst);
    if ((unsigned)dst < NN) atomicAdd(&g_count[dst], 1);
}

// ---------------------------------------------------------------------------
// scan1: per-block exclusive scan (1024 elems/block) + block sums
// ---------------------------------------------------------------------------
__global__ __launch_bounds__(1024) void scan1_kernel() {
    __shared__ int sh[1024];
    int t = threadIdx.x;
    int i = blockIdx.x * 1024 + t;
    int c = (i < NN) ? g_count[i] : 0;
    sh[t] = c;
    __syncthreads();
#pragma unroll
    for (int off = 1; off < 1024; off <<= 1) {
        int v = (t >= off) ? sh[t - off] : 0;
        __syncthreads();
        sh[t] += v;
        __syncthreads();
    }
    if (i < NN) g_off[i] = sh[t] - c;        // exclusive, block-local
    if (t == 1023) g_bsum[blockIdx.x] = sh[1023];
}

// ---------------------------------------------------------------------------
// scan23: every block re-scans the 98 block sums locally (trivial), adds its
// own exclusive prefix to its 1024-elem chunk, materializes cursors.
// Last block also writes the grand total to g_off[NN].
// ---------------------------------------------------------------------------
__global__ __launch_bounds__(128) void scan23_kernel() {
    __shared__ int sh[128];
    int t = threadIdx.x;
    int v = (t < SCAN_BLOCKS) ? g_bsum[t] : 0;
    sh[t] = v;
    __syncthreads();
#pragma unroll
    for (int off = 1; off < 128; off <<= 1) {
        int p = (t >= off) ? sh[t - off] : 0;
        __syncthreads();
        sh[t] += p;
        __syncthreads();
    }
    int bpre = sh[blockIdx.x] - g_bsum[blockIdx.x];  // exclusive prefix of this block
#pragma unroll 1
    for (int k = t; k < 1024; k += 128) {
        int i = blockIdx.x * 1024 + k;
        if (i < NN) {
            int o = g_off[i] + bpre;
            g_off[i] = o;
            g_cur[i] = o;
        }
    }
    if (blockIdx.x == SCAN_BLOCKS - 1 && t == 127) g_off[NN] = sh[127];
}

__global__ void fill_kernel(const int* __restrict__ ei32) {
    int e = blockIdx.x * blockDim.x + threadIdx.x;
    if (e >= EE) return;
    int src, dst;
    load_edge(ei32, e, src, dst);
    if ((unsigned)dst >= NN) return;
    int pos = atomicAdd(&g_cur[dst], 1);
    g_csr[pos] = src;
}

// ---------------------------------------------------------------------------
// Pull-aggregate (R7, verified).  One warp per 2 nodes; 16 lanes own one
// float4 each; writes MEAN once, no atomics.
// ---------------------------------------------------------------------------
__global__ __launch_bounds__(256) void pull_kernel(const float4* __restrict__ x4) {
    int gw = (blockIdx.x * blockDim.x + threadIdx.x) >> 5;   // global warp id
    int lane = threadIdx.x & 31;
    int n = gw * 2 + (lane >> 4);
    int hl = lane & 15;
    if (n >= NN) return;

    int s = g_off[n];
    int epos = g_off[n + 1];
    float4 acc = make_float4(0.f, 0.f, 0.f, 0.f);
#pragma unroll 4
    for (int p = s; p < epos; p++) {
        int src = __ldg(&g_csr[p]);
        if ((unsigned)src < NN) {
            float4 v = __ldg(&x4[(size_t)src * 16 + hl]);
            acc.x += v.x; acc.y += v.y; acc.z += v.z; acc.w += v.w;
        }
    }
    float inv = 1.0f / fmaxf((float)(epos - s), 1.0f);
    reinterpret_cast<float4*>(g_agg)[(size_t)n * 16 + hl] =
        make_float4(acc.x * inv, acc.y * inv, acc.z * inv, acc.w * inv);
}

// ---------------------------------------------------------------------------
// Fused update + head, 128 threads (R7 GEMM config), static smem ~43.5 KB.
// Phase B: GEMM (4 threads per 4-node group, 16-wide j-quarter each).
// Phase C: stage x_new into the (now dead) Ws/Bs pool, pitch 68.
// Phase D: head, 1 thread per local node, x_new from smem.
// No early returns (syncthreads after phase B/C); all loads clamped,
// all stores guarded.
// ---------------------------------------------------------------------------
__global__ __launch_bounds__(128) void update_head_kernel(
    const float* __restrict__ u,
    const float* __restrict__ W,
    const float* __restrict__ B,
    const float* __restrict__ b,
    const float* __restrict__ Wp,
    const float* __restrict__ bp,
    float* __restrict__ out) {
    __shared__ float pool[8704];       // Ws[0,4096) | Bs[4096,8192); reused for x_new[128][68]
    __shared__ float Wps[HH * PP];     // 8 KB
    __shared__ float bs[HH];
    __shared__ float bps[PP];

    float* Ws  = pool;
    float* Bsh = pool + 4096;

    int tid = threadIdx.x;
    for (int i = tid; i < HH * HH; i += 128) { Ws[i] = W[i]; Bsh[i] = B[i]; }
    for (int i = tid; i < HH * PP; i += 128) Wps[i] = Wp[i];
    if (tid < HH) bs[tid] = b[tid];
    if (tid < PP) bps[tid] = bp[tid];
    __syncthreads();

    int grp = tid >> 2;                 // 0..31  -> node group
    int jq  = tid & 3;                  // j-quarter: [jq*16, jq*16+16)
    int n0  = blockIdx.x * 128 + grp * 4;
    int nn[4];
#pragma unroll
    for (int i = 0; i < 4; i++) nn[i] = min(n0 + i, NN - 1);

    const float4* Ws4 = reinterpret_cast<const float4*>(Ws);
    const float4* Bs4 = reinterpret_cast<const float4*>(Bsh);
    const float4* mean4 = reinterpret_cast<const float4*>(g_agg);
    const float4* u4    = reinterpret_cast<const float4*>(u);

    float acc[4][16];
#pragma unroll
    for (int i = 0; i < 4; i++)
#pragma unroll
        for (int j = 0; j < 16; j++) acc[i][j] = bs[jq * 16 + j];

#pragma unroll 1
    for (int kc = 0; kc < 16; kc++) {
        float4 mv[4], uv[4];
#pragma unroll
        for (int i = 0; i < 4; i++) {
            mv[i] = __ldg(&mean4[(size_t)nn[i] * 16 + kc]);
            uv[i] = __ldg(&u4[(size_t)nn[i] * 16 + kc]);
        }
#pragma unroll
        for (int q = 0; q < 4; q++) {
            int base = (kc * 4 + q) * 16 + jq * 4;
            float4 w0 = Ws4[base + 0], w1 = Ws4[base + 1];
            float4 w2 = Ws4[base + 2], w3 = Ws4[base + 3];
            float4 b0 = Bs4[base + 0], b1 = Bs4[base + 1];
            float4 b2 = Bs4[base + 2], b3 = Bs4[base + 3];
#pragma unroll
            for (int i = 0; i < 4; i++) {
                float mk = reinterpret_cast<const float*>(&mv[i])[q];
                float uk = reinterpret_cast<const float*>(&uv[i])[q];
                acc[i][0]  += mk * w0.x + uk * b0.x;
                acc[i][1]  += mk * w0.y + uk * b0.y;
                acc[i][2]  += mk * w0.z + uk * b0.z;
                acc[i][3]  += mk * w0.w + uk * b0.w;
                acc[i][4]  += mk * w1.x + uk * b1.x;
                acc[i][5]  += mk * w1.y + uk * b1.y;
                acc[i][6]  += mk * w1.z + uk * b1.z;
                acc[i][7]  += mk * w1.w + uk * b1.w;
                acc[i][8]  += mk * w2.x + uk * b2.x;
                acc[i][9]  += mk * w2.y + uk * b2.y;
                acc[i][10] += mk * w2.z + uk * b2.z;
                acc[i][11] += mk * w2.w + uk * b2.w;
                acc[i][12] += mk * w3.x + uk * b3.x;
                acc[i][13] += mk * w3.y + uk * b3.y;
                acc[i][14] += mk * w3.z + uk * b3.z;
                acc[i][15] += mk * w3.w + uk * b3.w;
            }
        }
    }

    // ReLU + write x_new to gmem (guarded)
#pragma unroll
    for (int i = 0; i < 4; i++)
#pragma unroll
        for (int j = 0; j < 16; j++) acc[i][j] = fmaxf(acc[i][j], 0.f);

#pragma unroll
    for (int i = 0; i < 4; i++) {
        if (n0 + i < NN) {
            float4* o = reinterpret_cast<float4*>(out) + (size_t)(n0 + i) * 16 + jq * 4;
#pragma unroll
            for (int j4 = 0; j4 < 4; j4++)
                o[j4] = make_float4(acc[i][j4 * 4 + 0], acc[i][j4 * 4 + 1],
                                    acc[i][j4 * 4 + 2], acc[i][j4 * 4 + 3]);
        }
    }

    // ---- stage x_new into pool (Ws/Bs now dead) ----
    __syncthreads();
#pragma unroll
    for (int i = 0; i < 4; i++) {
        int nl = grp * 4 + i;
#pragma unroll
        for (int j4 = 0; j4 < 4; j4++)
            *reinterpret_cast<float4*>(&pool[nl * 68 + jq * 16 + j4 * 4]) =
                make_float4(acc[i][j4 * 4 + 0], acc[i][j4 * 4 + 1],
                            acc[i][j4 * 4 + 2], acc[i][j4 * 4 + 3]);
    }
    __syncthreads();

    // ---- head: 1 thread per local node, x_new row from smem ----
    int n = blockIdx.x * 128 + tid;
    const float4* Wps4 = reinterpret_cast<const float4*>(Wps);

    float yacc[PP];
#pragma unroll
    for (int p = 0; p < PP; p++) yacc[p] = bps[p];

#pragma unroll 1
    for (int jc = 0; jc < 16; jc++) {
        float4 xv = *reinterpret_cast<const float4*>(&pool[tid * 68 + jc * 4]);
        float xs[4] = {xv.x, xv.y, xv.z, xv.w};
#pragma unroll
        for (int q = 0; q < 4; q++) {
            int j = jc * 4 + q;
#pragma unroll
            for (int p4 = 0; p4 < 8; p4++) {
                float4 wp = Wps4[j * 8 + p4];
                yacc[p4 * 4 + 0] += xs[q] * wp.x;
                yacc[p4 * 4 + 1] += xs[q] * wp.y;
                yacc[p4 * 4 + 2] += xs[q] * wp.z;
                yacc[p4 * 4 + 3] += xs[q] * wp.w;
            }
        }
    }

    if (n < NN) {
        float4* outy4 = reinterpret_cast<float4*>(out + (size_t)NN * HH) + (size_t)n * 8;
#pragma unroll
        for (int p4 = 0; p4 < 8; p4++)
            outy4[p4] = make_float4(yacc[p4 * 4 + 0], yacc[p4 * 4 + 1],
                                    yacc[p4 * 4 + 2], yacc[p4 * 4 + 3]);
    }
}

// ---------------------------------------------------------------------------
// Launch
// Inputs: x, u, edge_index ([2,E], int32/int64 autodetected), W, B, b, Wp, bp
// Output: x_new [N*64] then y [N*32]  (float32)
// ---------------------------------------------------------------------------
extern "C" void kernel_launch(void* const* d_in, const int* in_sizes, int n_in,
                              void* d_out, int out_size) {
    const float* x       = (const float*)d_in[0];
    const float* u       = (const float*)d_in[1];
    const int*   ei32    = (const int*)d_in[2];
    const float* W       = (const float*)d_in[3];
    const float* B       = (const float*)d_in[4];
    const float* b       = (const float*)d_in[5];
    const float* Wp      = (const float*)d_in[6];
    const float* bp      = (const float*)d_in[7];
    float* out           = (float*)d_out;

    zero_counts_kernel<<<(NN + 255) / 256, 256>>>(ei32);
    hist_kernel<<<(EE + 255) / 256, 256>>>(ei32);
    scan1_kernel<<<SCAN_BLOCKS, 1024>>>();
    scan23_kernel<<<SCAN_BLOCKS, 128>>>();
    fill_kernel<<<(EE + 255) / 256, 256>>>(ei32);

    long long pull_threads = (long long)((NN + 1) / 2) * 32;
    pull_kernel<<<(int)((pull_threads + 255) / 256), 256>>>((const float4*)x);

    update_head_kernel<<<(NN + 127) / 128, 128>>>(u, W, B, b, Wp, bp, out);
}